// round 12
// baseline (speedup 1.0000x reference)
#include <cuda_runtime.h>
#include <cuda_fp16.h>
#include <stdint.h>

#define B_   8
#define C_   64
#define NV   40962
#define K_   7
#define CK   448
#define VT   128            // vertices per main CTA

// ---------------------------------------------------------------------------
// Static device scratch (no runtime allocation allowed)
// ---------------------------------------------------------------------------
__device__ __align__(256) __half g_xh[(size_t)B_ * NV * C_];   // [b][n][c] fp16, 42 MB
__device__ __align__(256) unsigned char g_wf[K_ * 8192];       // [k] 64x64 fp16 tile, SW128

// ---------------------------------------------------------------------------
// PTX helpers (baseline-sm_100-legal: cp.async, ldmatrix, mma.sync fp16)
// ---------------------------------------------------------------------------
__device__ __forceinline__ uint32_t smem_u32(const void* p) {
    uint32_t a;
    asm("{ .reg .u64 t; cvta.to.shared.u64 t, %1; cvt.u32.u64 %0, t; }" : "=r"(a) : "l"(p));
    return a;
}
#define CP16(dst, src) \
    asm volatile("cp.async.cg.shared.global [%0], [%1], 16;" :: "r"(dst), "l"(src) : "memory")
#define CP_COMMIT() asm volatile("cp.async.commit_group;" ::: "memory")
#define CP_WAIT1()  asm volatile("cp.async.wait_group 1;" ::: "memory")
#define CP_WAIT0()  asm volatile("cp.async.wait_group 0;" ::: "memory")

#define LDM_X4(r0, r1, r2, r3, a) \
    asm volatile("ldmatrix.sync.aligned.m8n8.x4.shared.b16 {%0,%1,%2,%3}, [%4];" \
                 : "=r"(r0), "=r"(r1), "=r"(r2), "=r"(r3) : "r"(a))

#define MMA16816F(d, a, b) \
    asm volatile("mma.sync.aligned.m16n8k16.row.col.f32.f16.f16.f32 " \
                 "{%0,%1,%2,%3}, {%4,%5,%6,%7}, {%8,%9}, {%0,%1,%2,%3};" \
                 : "+f"((d)[0]), "+f"((d)[1]), "+f"((d)[2]), "+f"((d)[3]) \
                 : "r"((a)[0]), "r"((a)[1]), "r"((a)[2]), "r"((a)[3]), \
                   "r"((b)[0]), "r"((b)[1]))

#define SWZ(o) ((o) ^ (((o) >> 3) & 0x70))

// ---------------------------------------------------------------------------
// SMEM layout (bytes): A stages 2x16K | W all-k 56K | neigh | bias
// ---------------------------------------------------------------------------
#define SOFF_A(p)    ((p) * 16384)
#define SOFF_WALL    32768                   // 7 * 8192 = 57344
#define SOFF_NEIGH   90112                   // VT*K_*4 = 3584
#define SOFF_BIAS    93696                   // 256
#define SMEM_TOTAL   93952                   // 2 CTAs/SM: 187.9KB

// ---------------------------------------------------------------------------
// Kernel 1: transpose x [B,C,N] -> g_xh [B,N,C] fp16, vectorized half2 stores
// Block: 256 threads, tile = 64c x 32n.
// ---------------------------------------------------------------------------
__global__ void xprep_kernel(const float* __restrict__ x) {
    __shared__ float tile[64][33];
    const int b  = blockIdx.y;
    const int n0 = blockIdx.x * 32;
    const int t  = threadIdx.x;
    const int tx = t & 31;        // n within tile (load), c-pair (store)
    const int cy = t >> 5;        // 0..7

    #pragma unroll
    for (int s = 0; s < 8; s++) {
        const int c = cy * 8 + s;                 // 0..63
        const int n = n0 + tx;
        float v = 0.0f;
        if (n < NV) v = x[((size_t)b * C_ + c) * NV + n];
        tile[c][tx] = v;
    }
    __syncthreads();

    // store: warp covers 32 consecutive c-pairs of one n -> one 128B line
    const int cp = tx;            // c-pair 0..31
    const int nl = cy;            // base n 0..7
    #pragma unroll
    for (int m = 0; m < 4; m++) {
        const int n = nl + m * 8;                 // 0..31
        if (n0 + n < NV) {
            const __half2 h = __floats2half2_rn(tile[2 * cp][n], tile[2 * cp + 1][n]);
            *(__half2*)(g_xh + ((size_t)b * NV + n0 + n) * C_ + 2 * cp) = h;
        }
    }
}

// ---------------------------------------------------------------------------
// Kernel 2: W [o][c*7+k] -> g_wf [k] 64x64 fp16 K-major tile, SW128 rows
// ---------------------------------------------------------------------------
__global__ void wprep_kernel(const float* __restrict__ W) {
    const int e = blockIdx.x * 256 + threadIdx.x;   // over 7*64*64
    if (e >= K_ * C_ * C_) return;
    const int c = e & 63;
    const int o = (e >> 6) & 63;
    const int k = e >> 12;
    const __half h = __float2half_rn(W[o * CK + c * K_ + k]);
    const uint32_t sw = SWZ((uint32_t)(o * 128 + c * 2));
    *(__half*)(g_wf + (size_t)k * 8192 + sw) = h;
}

// ---------------------------------------------------------------------------
// Kernel 3: gather + fp16 mma.sync. 1 CTA = (batch, 128 vertices).
// 256 threads / 8 warps; warp = 32 vertices x 32 outputs; 2 CTAs/SM.
// W for ALL k resident in smem (loaded once); only A double-buffered.
// ---------------------------------------------------------------------------
extern __shared__ char smem_raw[];

// Coalesced gather: each warp instruction covers 4 rows, 8 lanes x 16B
// contiguous per row -> 4 distinct 128B lines per instruction (line minimum).
__device__ __forceinline__ void stage_A(
    int p, int k, int vmax, const int* sN,
    const __half* xhb, uint32_t sb, int tid)
{
    const int w   = tid >> 5;          // warp 0..7
    const int sub = (tid & 31) >> 3;   // row within instr 0..3
    const int ch  = tid & 7;           // 16B chunk 0..7
    #pragma unroll
    for (int i = 0; i < 4; i++) {
        const int v = i * 32 + w * 4 + sub;      // 0..127
        const int j = (v < vmax) ? sN[v * K_ + k] : 0;
        const char* src = (const char*)(xhb + (size_t)j * C_) + ch * 16;
        CP16(sb + SOFF_A(p) + SWZ((uint32_t)(v * 128 + ch * 16)), src);
    }
}

__global__ __launch_bounds__(256, 2)
void iconv_mma_kernel(const int* __restrict__ neigh,
                      const float* __restrict__ bias,
                      float* __restrict__ out) {
    const uint32_t sb = smem_u32(smem_raw);
    const int tid  = threadIdx.x;
    const int lane = tid & 31;
    const int wid  = tid >> 5;
    const int b    = blockIdx.y;
    const int n0   = blockIdx.x * VT;
    const int vmax = min(VT, NV - n0);

    // stage bias + neighbor indices
    if (tid < C_) ((float*)(smem_raw + SOFF_BIAS))[tid] = bias[tid];
    {
        int* sN = (int*)(smem_raw + SOFF_NEIGH);
        const int lim = vmax * K_;
        #pragma unroll
        for (int i = 0; i < 4; i++) {
            const int q = tid + i * 256;
            if (q < VT * K_) sN[q] = (q < lim) ? neigh[(size_t)n0 * K_ + q] : 0;
        }
    }
    __syncthreads();

    const int* sN = (const int*)(smem_raw + SOFF_NEIGH);
    const __half* xhb = g_xh + (size_t)b * NV * C_;

    // prologue: ALL W tiles (56KB, pre-swizzled, linear) + A(k=0), one group
    {
        const char* wsrc = (const char*)g_wf;
        const uint32_t wdst = sb + SOFF_WALL;
        #pragma unroll
        for (int i = 0; i < 14; i++) {             // 3584 CP16 over 256 threads
            const int idx = tid + i * 256;
            CP16(wdst + (uint32_t)idx * 16, wsrc + (size_t)idx * 16);
        }
        stage_A(0, 0, vmax, sN, xhb, sb, tid);
        CP_COMMIT();
    }

    // warp tiling: 4 v-groups x 2 o-groups
    const int vg = wid >> 1;                  // vertices [vg*32, +32)
    const int og = wid & 1;                   // outputs  [og*32, +32)

    const int rowA = vg * 32 + (lane & 15);               // + i*16
    const uint32_t halfA = (uint32_t)((lane >> 4) * 16);
    const int rowB = (lane & 7) + ((lane >> 4) << 3);     // + og*32 + jp*16
    const uint32_t halfB = (uint32_t)(((lane >> 3) & 1) * 16);

    float acc[2][4][4];
    #pragma unroll
    for (int i = 0; i < 2; i++)
        #pragma unroll
        for (int j = 0; j < 4; j++)
            #pragma unroll
            for (int r = 0; r < 4; r++) acc[i][j][r] = 0.0f;

    for (int k = 0; k < K_; k++) {
        const int p = k & 1;
        if (k < K_ - 1) {
            stage_A(p ^ 1, k + 1, vmax, sN, xhb, sb, tid);
            CP_COMMIT();
            CP_WAIT1();        // at k=0 this also covers the W+A0 group
        } else {
            CP_WAIT0();
        }
        __syncthreads();

        const uint32_t aB = sb + SOFF_A(p);
        const uint32_t wB = sb + SOFF_WALL + (uint32_t)k * 8192;

        #pragma unroll
        for (int kk = 0; kk < 4; kk++) {
            uint32_t aF[2][4];
            #pragma unroll
            for (int i = 0; i < 2; i++) {
                // half-offset added BEFORE the swizzle (no-carry there)
                const uint32_t offA =
                    SWZ((uint32_t)((rowA + i * 16) * 128 + kk * 32) + halfA);
                LDM_X4(aF[i][0], aF[i][1], aF[i][2], aF[i][3], aB + offA);
            }
            uint32_t bF[4][2];
            #pragma unroll
            for (int jp = 0; jp < 2; jp++) {
                const uint32_t offB =
                    SWZ((uint32_t)((og * 32 + jp * 16 + rowB) * 128 + kk * 32) + halfB);
                uint32_t r0, r1, r2, r3;
                LDM_X4(r0, r1, r2, r3, wB + offB);
                bF[2 * jp][0]     = r0;  bF[2 * jp][1]     = r1;
                bF[2 * jp + 1][0] = r2;  bF[2 * jp + 1][1] = r3;
            }
            #pragma unroll
            for (int i = 0; i < 2; i++)
                #pragma unroll
                for (int j = 0; j < 4; j++)
                    MMA16816F(acc[i][j], aF[i], bF[j]);
        }
        __syncthreads();   // done reading A buf p before it is overwritten
    }

    // ---- epilogue: regs -> smem stage [v*65 + o] -> coalesced stores ----
    // st spans 33,280 B from smem base: overlaps A stages + first 512B of W
    // (both dead by now); BIAS/NEIGH live higher and are untouched.
    {
        float* st = (float*)smem_raw;
        const int gid = lane >> 2;
        const int tg  = lane & 3;
        #pragma unroll
        for (int i = 0; i < 2; i++)
            #pragma unroll
            for (int j = 0; j < 4; j++)
                #pragma unroll
                for (int r = 0; r < 4; r++) {
                    const int v = vg * 32 + i * 16 + gid + (r >> 1) * 8;
                    const int o = og * 32 + j * 8 + 2 * tg + (r & 1);
                    st[v * 65 + o] = acc[i][j][r];
                }
        __syncthreads();

        const float* sBias = (const float*)(smem_raw + SOFF_BIAS);
        const int v  = tid & 127;          // 128 consecutive v -> full coalescing
        const int oh = (tid >> 7) * 32;    // output half
        if (v < vmax) {
            #pragma unroll
            for (int oo = 0; oo < 32; oo++) {
                const int o = oh + oo;
                out[((size_t)b * C_ + o) * NV + n0 + v] = st[v * 65 + o] + sBias[o];
            }
        }
    }
}

// ---------------------------------------------------------------------------
// Launch
// ---------------------------------------------------------------------------
extern "C" void kernel_launch(void* const* d_in, const int* in_sizes, int n_in,
                              void* d_out, int out_size) {
    const float* x     = (const float*)d_in[0];
    const int*   neigh = (const int*)d_in[1];    // JAX x64 disabled -> int32
    const float* W     = (const float*)d_in[2];
    const float* bias  = (const float*)d_in[3];
    float*       out   = (float*)d_out;

    cudaFuncSetAttribute(iconv_mma_kernel,
                         cudaFuncAttributeMaxDynamicSharedMemorySize, SMEM_TOTAL);

    dim3 tgrid((NV + 31) / 32, B_);              // (1281, 8)
    xprep_kernel<<<tgrid, 256>>>(x);

    wprep_kernel<<<(K_ * C_ * C_ + 255) / 256, 256>>>(W);

    dim3 mgrid((NV + VT - 1) / VT, B_);          // (321, 8)
    iconv_mma_kernel<<<mgrid, 256, SMEM_TOTAL>>>(neigh, bias, out);
}